// round 12
// baseline (speedup 1.0000x reference)
#include <cuda_runtime.h>
#include <cuda_fp16.h>
#include <cstdint>

#define NUM_E 8
#define NUM_T 8192
#define NUM_K 2048
#define NUM_N 2048
#define NUM_G 16

constexpr int BM = 128;
constexpr int BN = 128;
constexpr int BK = 64;        // k per pipeline stage
constexpr int BKP = BK / 2;   // k-pair uints per row = 32
constexpr int PAD = 4;        // uint row stride 36 -> conflict-free ldmatrix
constexpr int ROWSTRIDE = BKP + PAD;               // 36 uints
constexpr int STAGE_UINTS = BM * ROWSTRIDE;        // 4608 uints = 18432 B
constexpr int STAGES = 2;
constexpr int THREADS = 256;
constexpr int KITERS = NUM_K / BK;                 // 32
constexpr int GEMM_SMEM = (2 * STAGES * STAGE_UINTS) * 4 + BM * 4;  // 74240 B
constexpr int GEMM_GRID = 296;                     // persistent: 2 CTAs/SM x 148

constexpr int WX_BLOCKS = 2048;
constexpr int AP_BLOCKS = (NUM_T * NUM_K / 8) / 256;   // 8192
constexpr int PREP_BLOCKS = 1 + WX_BLOCKS + AP_BLOCKS; // 10241

// ---------------- static device scratch (no allocations allowed) ----------------
__device__ int    g_counts[NUM_E];
__device__ int    g_offsets[NUM_E];
__device__ int    g_sorted[NUM_T];
__device__ int    g_nrow;                              // number of active (e, m-tile) rows
__device__ int    g_rowte[128];                        // (e << 16) | mtile
__device__ __half g_Ah[(size_t)NUM_T * NUM_K];         // state fp16, 32 MB
__device__ __half g_Bh[(size_t)NUM_E * NUM_N * NUM_K]; // dequant W [e][n][k], 64 MB

// ---------------- fused prep: route+tilelist (1 block) + wexpand (2048) + aprep (8192) --------
__global__ __launch_bounds__(THREADS)
void k_prep(const float* __restrict__ state,
            const int*   __restrict__ wp,
            const float* __restrict__ ws,
            const int*   __restrict__ zp,
            const int*   __restrict__ gidx,
            const int*   __restrict__ expert_ids)
{
    __shared__ union {
        struct { int cnt[NUM_E]; int cur[NUM_E]; } route;
        struct {
            uint2    zs[NUM_G][64];
            int      gsh[128];
            unsigned sm[128][65];
        } wx;
    } sh;

    const int b = blockIdx.x;
    const int t = threadIdx.x;

    if (b == 0) {
        // ---- routing + tile list ----
        if (t < NUM_E) sh.route.cnt[t] = 0;
        __syncthreads();
        for (int i = t; i < NUM_T; i += THREADS) atomicAdd(&sh.route.cnt[expert_ids[i]], 1);
        __syncthreads();
        if (t == 0) {
            int acc = 0, nr = 0;
            for (int e = 0; e < NUM_E; e++) {
                int c = sh.route.cnt[e];
                g_counts[e] = c; g_offsets[e] = acc; sh.route.cur[e] = acc;
                acc += c;
                int nmt = (c + BM - 1) / BM;
                for (int mt = 0; mt < nmt; mt++) g_rowte[nr++] = (e << 16) | mt;
            }
            g_nrow = nr;
        }
        __syncthreads();
        for (int i = t; i < NUM_T; i += THREADS) {
            int p = atomicAdd(&sh.route.cur[expert_ids[i]], 1);
            g_sorted[p] = i;
        }
        return;
    }

    const int j = b - 1;
    const int q = j / 5, rm = j % 5;     // interleave: 1 wexpand per 4 aprep

    if (rm == 0) {
        // ---- wexpand block q = ((e*16 + nb)*16 + kb) ----
        const int kb = q & 15;
        const int nb = (q >> 4) & 15;
        const int e  = q >> 8;

        for (int i = t; i < NUM_G * 64; i += THREADS) {
            int g = i >> 6, np = i & 63;
            const size_t base = (size_t)(e * NUM_G + g) * NUM_N + nb * 128 + 2 * np;
            unsigned z2 = (0x6400u | (unsigned)zp[base]) | ((0x6400u | (unsigned)zp[base + 1]) << 16);
            __half2 s2h = __floats2half2_rn(ws[base], ws[base + 1]);
            uint2 v; v.x = z2; v.y = *reinterpret_cast<unsigned*>(&s2h);
            sh.wx.zs[g][np] = v;
        }
        if (t < 128) sh.wx.gsh[t] = gidx[kb * 128 + t];
        __syncthreads();

        const int npl = t & 63;
        const int rq  = t >> 6;
        const int npg = nb * 64 + npl;
        const uint2* wp2 = reinterpret_cast<const uint2*>(wp + (size_t)e * (NUM_K / 8) * NUM_N);

#pragma unroll
        for (int p = 0; p < 4; p++) {
            const int rowl = rq * 4 + p;
            const int rowg = kb * 16 + rowl;
            uint2 w = wp2[(size_t)rowg * (NUM_N / 2) + npg];
            unsigned pr[8];
#pragma unroll
            for (int jj = 0; jj < 8; jj++) {
                uint2 zsv = sh.wx.zs[sh.wx.gsh[rowl * 8 + jj]][npl];
                unsigned x0 = w.x >> (4 * jj), x1 = w.y >> (4 * jj);
                unsigned h2 = ((x0 & 15u) | 0x6400u) | (((x1 & 15u) | 0x6400u) << 16);
                __half2 v = __hsub2(*reinterpret_cast<__half2*>(&h2),
                                    *reinterpret_cast<__half2*>(&zsv.x));   // exact q - zp
                v = __hmul2(v, *reinterpret_cast<__half2*>(&zsv.y));
                pr[jj] = *reinterpret_cast<unsigned*>(&v);
            }
#pragma unroll
            for (int qq = 0; qq < 4; qq++) {
                sh.wx.sm[2 * npl    ][rowl * 4 + qq] = __byte_perm(pr[2 * qq], pr[2 * qq + 1], 0x5410);
                sh.wx.sm[2 * npl + 1][rowl * 4 + qq] = __byte_perm(pr[2 * qq], pr[2 * qq + 1], 0x7632);
            }
        }
        __syncthreads();

        __half* Bg = g_Bh + ((size_t)e * NUM_N + (size_t)nb * 128) * NUM_K + (size_t)kb * 128;
#pragma unroll
        for (int i = 0; i < 8; i++) {
            int item = t + i * THREADS;
            int n  = item >> 4;
            int q4 = item & 15;
            uint4 v = make_uint4(sh.wx.sm[n][q4 * 4], sh.wx.sm[n][q4 * 4 + 1],
                                 sh.wx.sm[n][q4 * 4 + 2], sh.wx.sm[n][q4 * 4 + 3]);
            *reinterpret_cast<uint4*>(Bg + (size_t)n * NUM_K + q4 * 8) = v;
        }
    } else {
        // ---- aprep ----
        const int apb = j - q - 1;
        size_t i = (size_t)apb * THREADS + t;
        const float4* s4 = reinterpret_cast<const float4*>(state);
        float4 a = s4[i * 2], bb = s4[i * 2 + 1];
        __half2 h0 = __floats2half2_rn(a.x, a.y),  h1 = __floats2half2_rn(a.z, a.w);
        __half2 h2 = __floats2half2_rn(bb.x, bb.y), h3 = __floats2half2_rn(bb.z, bb.w);
        uint4 o;
        o.x = *reinterpret_cast<unsigned*>(&h0);
        o.y = *reinterpret_cast<unsigned*>(&h1);
        o.z = *reinterpret_cast<unsigned*>(&h2);
        o.w = *reinterpret_cast<unsigned*>(&h3);
        reinterpret_cast<uint4*>(g_Ah)[i] = o;
    }
}

// ---------------- asm helpers ----------------
__device__ __forceinline__ void cpa16(void* dst, const void* src) {
    unsigned d = (unsigned)__cvta_generic_to_shared(dst);
    asm volatile("cp.async.cg.shared.global [%0], [%1], 16;" :: "r"(d), "l"(src));
}
__device__ __forceinline__ void cp_commit() { asm volatile("cp.async.commit_group;"); }
template <int N>
__device__ __forceinline__ void cp_wait() { asm volatile("cp.async.wait_group %0;" :: "n"(N)); }

__device__ __forceinline__ void ldsm4(unsigned& r0, unsigned& r1, unsigned& r2, unsigned& r3,
                                      unsigned addr) {
    asm volatile("ldmatrix.sync.aligned.m8n8.x4.shared.b16 {%0,%1,%2,%3}, [%4];"
                 : "=r"(r0), "=r"(r1), "=r"(r2), "=r"(r3) : "r"(addr));
}

#define MMA_F16(d, a, b)                                                        \
    asm volatile(                                                               \
        "mma.sync.aligned.m16n8k16.row.col.f32.f16.f16.f32 "                    \
        "{%0,%1,%2,%3}, {%4,%5,%6,%7}, {%8,%9}, {%0,%1,%2,%3};"                 \
        : "+f"(d[0]), "+f"(d[1]), "+f"(d[2]), "+f"(d[3])                        \
        : "r"(a[0]), "r"(a[1]), "r"(a[2]), "r"(a[3]), "r"(b[0]), "r"(b[1]))

// ---------------- persistent grouped GEMM: BK=64, 2-stage, 8 warps, 64x32 warp tiles ----------
__global__ __launch_bounds__(THREADS, 2)
void k_gemm(float* __restrict__ out) {
    extern __shared__ __align__(16) unsigned dsm[];
    unsigned* As = dsm;                              // [STAGES][BM][ROWSTRIDE]
    unsigned* Bs = dsm + STAGES * STAGE_UINTS;       // [STAGES][BN][ROWSTRIDE]
    int*      toks = (int*)(dsm + 2 * STAGES * STAGE_UINTS);

    const int tid  = threadIdx.x;
    const int wid  = tid >> 5;
    const int lane = tid & 31;
    const int wm   = (wid >> 2) * 64;
    const int wn   = (wid & 3) * 32;
    const int g8   = lane >> 2;          // 0..7
    const int tig  = lane & 3;           // 0..3

    const int r  = tid >> 1;             // load row 0..127
    const int kc = (tid & 1) * 4;        // 4 x 16B chunks per thread (8 chunks/row)

    // per-lane ldmatrix base addresses (slot 0), bytes
    const unsigned abase = (unsigned)__cvta_generic_to_shared(As);
    const unsigned bbase = (unsigned)__cvta_generic_to_shared(Bs);
    const int mtx = lane >> 3;           // 0..3
    const int lr  = lane & 7;
    unsigned aaddr[4];
#pragma unroll
    for (int mi = 0; mi < 4; mi++)
        aaddr[mi] = abase + (((wm + mi * 16 + (mtx & 1) * 8 + lr) * ROWSTRIDE
                              + (mtx >> 1) * 4) << 2);
    unsigned baddr[2];
#pragma unroll
    for (int nip = 0; nip < 2; nip++)
        baddr[nip] = bbase + (((wn + nip * 16 + (mtx >> 1) * 8 + lr) * ROWSTRIDE
                               + (mtx & 1) * 4) << 2);

    const int ntiles = g_nrow * (NUM_N / BN);

    for (int tl = blockIdx.x; tl < ntiles; tl += GEMM_GRID) {
        const int rt    = tl >> 4;             // row-tile index (rowtile-major: n varies fastest)
        const int nbase = (tl & 15) * BN;
        const int ete   = g_rowte[rt];
        const int e     = ete >> 16;
        const int mbase = (ete & 0xFFFF) * BM;
        const int cnt   = g_counts[e];
        const int off   = g_offsets[e];

        __syncthreads();   // previous tile fully consumed (toks + smem reuse safe)
        if (tid < BM) {
            int gm = mbase + tid;
            toks[tid] = (gm < cnt) ? g_sorted[off + gm] : g_sorted[off];
        }
        __syncthreads();

        const __half* Bg   = g_Bh + ((size_t)e * NUM_N + nbase) * NUM_K;
        const __half* arow = g_Ah + (size_t)toks[r] * NUM_K;
        const __half* brow = Bg + (size_t)r * NUM_K;

        auto load_stage = [&](int s, int k0) {
            unsigned* a = As + s * STAGE_UINTS + r * ROWSTRIDE + kc * 4;
            unsigned* b = Bs + s * STAGE_UINTS + r * ROWSTRIDE + kc * 4;
#pragma unroll
            for (int c = 0; c < 4; c++) {
                cpa16(a + c * 4, arow + k0 + (kc + c) * 8);
                cpa16(b + c * 4, brow + k0 + (kc + c) * 8);
            }
        };

        float acc[4][4][4];
#pragma unroll
        for (int mi = 0; mi < 4; mi++)
#pragma unroll
            for (int ni = 0; ni < 4; ni++)
#pragma unroll
                for (int q = 0; q < 4; q++) acc[mi][ni][q] = 0.0f;

        load_stage(0, 0);
        cp_commit();

        for (int kt = 0; kt < KITERS; kt++) {
            const int s = kt & 1;
            cp_wait<0>();                // stage kt resident
            __syncthreads();             // visible to all; slot s^1 free (kt-1 consumed)
            if (kt + 1 < KITERS) { load_stage(s ^ 1, (kt + 1) * BK); }
            cp_commit();

            const unsigned soff = (unsigned)(s * STAGE_UINTS * 4);
#pragma unroll
            for (int ks = 0; ks < 4; ks++) {          // four k16 steps per stage
                const unsigned koff = soff + ks * 32; // 8 uints = 32 B
                unsigned af[4][4], bf[4][2];
#pragma unroll
                for (int mi = 0; mi < 4; mi++)
                    ldsm4(af[mi][0], af[mi][1], af[mi][2], af[mi][3], aaddr[mi] + koff);
#pragma unroll
                for (int nip = 0; nip < 2; nip++)
                    ldsm4(bf[2 * nip][0], bf[2 * nip][1], bf[2 * nip + 1][0], bf[2 * nip + 1][1],
                          baddr[nip] + koff);
#pragma unroll
                for (int mi = 0; mi < 4; mi++)
#pragma unroll
                    for (int ni = 0; ni < 4; ni++)
                        MMA_F16(acc[mi][ni], af[mi], bf[ni]);
            }
        }

        // epilogue: scatter rows to out[token][n]
#pragma unroll
        for (int mi = 0; mi < 4; mi++) {
            int rl0 = wm + mi * 16 + g8;
            int rl1 = rl0 + 8;
            bool v0 = (mbase + rl0) < cnt;
            bool v1 = (mbase + rl1) < cnt;
            int tok0 = toks[rl0];
            int tok1 = toks[rl1];
#pragma unroll
            for (int ni = 0; ni < 4; ni++) {
                int c = nbase + wn + ni * 8 + tig * 2;
                if (v0) *reinterpret_cast<float2*>(&out[(size_t)tok0 * NUM_N + c]) =
                    make_float2(acc[mi][ni][0], acc[mi][ni][1]);
                if (v1) *reinterpret_cast<float2*>(&out[(size_t)tok1 * NUM_N + c]) =
                    make_float2(acc[mi][ni][2], acc[mi][ni][3]);
            }
        }
    }
}

// ---------------- launch ----------------
extern "C" void kernel_launch(void* const* d_in, const int* in_sizes, int n_in,
                              void* d_out, int out_size) {
    const float* state      = (const float*)d_in[0];
    const int*   wpacked    = (const int*)  d_in[1];
    const float* wscale     = (const float*)d_in[2];
    const int*   zp         = (const int*)  d_in[3];
    const int*   g_idx      = (const int*)  d_in[4];
    const int*   expert_ids = (const int*)  d_in[5];
    float*       out        = (float*)d_out;

    cudaFuncSetAttribute(k_gemm, cudaFuncAttributeMaxDynamicSharedMemorySize, GEMM_SMEM);

    k_prep<<<PREP_BLOCKS, THREADS>>>(state, wpacked, wscale, zp, g_idx, expert_ids);
    k_gemm<<<GEMM_GRID, THREADS, GEMM_SMEM>>>(out);
}

// round 13
// speedup vs baseline: 1.0107x; 1.0107x over previous
#include <cuda_runtime.h>
#include <cuda_fp16.h>
#include <cstdint>

#define NUM_E 8
#define NUM_T 8192
#define NUM_K 2048
#define NUM_N 2048
#define NUM_G 16

constexpr int BM = 64;
constexpr int BN = 128;
constexpr int BK = 32;        // k per pipeline stage
constexpr int BKP = BK / 2;   // k-pair uints per row = 16
constexpr int PAD = 4;        // uint row stride 20 -> conflict-free ldmatrix
constexpr int ROWSTRIDE = BKP + PAD;               // 20 uints
constexpr int A_STAGE_UINTS = BM * ROWSTRIDE;      // 1280
constexpr int B_STAGE_UINTS = BN * ROWSTRIDE;      // 2560
constexpr int STAGES = 6;
constexpr int THREADS = 256;
constexpr int KITERS = NUM_K / BK;                 // 64
constexpr int GEMM_SMEM = (STAGES * (A_STAGE_UINTS + B_STAGE_UINTS)) * 4 + BM * 4;  // 92416 B
constexpr int GEMM_GRID = 296;                     // persistent: 2 CTAs/SM x 148

constexpr int WX_BLOCKS = 2048;
constexpr int AP_BLOCKS = (NUM_T * NUM_K / 8) / 256;   // 8192
constexpr int PREP_BLOCKS = 1 + WX_BLOCKS + AP_BLOCKS; // 10241

// ---------------- static device scratch (no allocations allowed) ----------------
__device__ int    g_counts[NUM_E];
__device__ int    g_offsets[NUM_E];
__device__ int    g_sorted[NUM_T];
__device__ int    g_nrow;                              // number of active (e, m-tile) rows
__device__ int    g_rowte[256];                        // (e << 16) | mtile
__device__ __half g_Ah[(size_t)NUM_T * NUM_K];         // state fp16, 32 MB
__device__ __half g_Bh[(size_t)NUM_E * NUM_N * NUM_K]; // dequant W [e][n][k], 64 MB

// ---------------- fused prep: route+tilelist (1 block) + wexpand (2048) + aprep (8192) --------
__global__ __launch_bounds__(THREADS)
void k_prep(const float* __restrict__ state,
            const int*   __restrict__ wp,
            const float* __restrict__ ws,
            const int*   __restrict__ zp,
            const int*   __restrict__ gidx,
            const int*   __restrict__ expert_ids)
{
    __shared__ union {
        struct { int cnt[NUM_E]; int cur[NUM_E]; } route;
        struct {
            uint2    zs[NUM_G][64];
            int      gsh[128];
            unsigned sm[128][65];
        } wx;
    } sh;

    const int b = blockIdx.x;
    const int t = threadIdx.x;

    if (b == 0) {
        // ---- routing + tile list ----
        if (t < NUM_E) sh.route.cnt[t] = 0;
        __syncthreads();
        for (int i = t; i < NUM_T; i += THREADS) atomicAdd(&sh.route.cnt[expert_ids[i]], 1);
        __syncthreads();
        if (t == 0) {
            int acc = 0, nr = 0;
            for (int e = 0; e < NUM_E; e++) {
                int c = sh.route.cnt[e];
                g_counts[e] = c; g_offsets[e] = acc; sh.route.cur[e] = acc;
                acc += c;
                int nmt = (c + BM - 1) / BM;
                for (int mt = 0; mt < nmt; mt++) g_rowte[nr++] = (e << 16) | mt;
            }
            g_nrow = nr;
        }
        __syncthreads();
        for (int i = t; i < NUM_T; i += THREADS) {
            int p = atomicAdd(&sh.route.cur[expert_ids[i]], 1);
            g_sorted[p] = i;
        }
        return;
    }

    const int j = b - 1;
    const int q = j / 5, rm = j % 5;     // interleave: 1 wexpand per 4 aprep

    if (rm == 0) {
        // ---- wexpand block q = ((e*16 + nb)*16 + kb) ----
        const int kb = q & 15;
        const int nb = (q >> 4) & 15;
        const int e  = q >> 8;

        for (int i = t; i < NUM_G * 64; i += THREADS) {
            int g = i >> 6, np = i & 63;
            const size_t base = (size_t)(e * NUM_G + g) * NUM_N + nb * 128 + 2 * np;
            unsigned z2 = (0x6400u | (unsigned)zp[base]) | ((0x6400u | (unsigned)zp[base + 1]) << 16);
            __half2 s2h = __floats2half2_rn(ws[base], ws[base + 1]);
            uint2 v; v.x = z2; v.y = *reinterpret_cast<unsigned*>(&s2h);
            sh.wx.zs[g][np] = v;
        }
        if (t < 128) sh.wx.gsh[t] = gidx[kb * 128 + t];
        __syncthreads();

        const int npl = t & 63;
        const int rq  = t >> 6;
        const int npg = nb * 64 + npl;
        const uint2* wp2 = reinterpret_cast<const uint2*>(wp + (size_t)e * (NUM_K / 8) * NUM_N);

#pragma unroll
        for (int p = 0; p < 4; p++) {
            const int rowl = rq * 4 + p;
            const int rowg = kb * 16 + rowl;
            uint2 w = wp2[(size_t)rowg * (NUM_N / 2) + npg];
            unsigned pr[8];
#pragma unroll
            for (int jj = 0; jj < 8; jj++) {
                uint2 zsv = sh.wx.zs[sh.wx.gsh[rowl * 8 + jj]][npl];
                unsigned x0 = w.x >> (4 * jj), x1 = w.y >> (4 * jj);
                unsigned h2 = ((x0 & 15u) | 0x6400u) | (((x1 & 15u) | 0x6400u) << 16);
                __half2 v = __hsub2(*reinterpret_cast<__half2*>(&h2),
                                    *reinterpret_cast<__half2*>(&zsv.x));   // exact q - zp
                v = __hmul2(v, *reinterpret_cast<__half2*>(&zsv.y));
                pr[jj] = *reinterpret_cast<unsigned*>(&v);
            }
#pragma unroll
            for (int qq = 0; qq < 4; qq++) {
                sh.wx.sm[2 * npl    ][rowl * 4 + qq] = __byte_perm(pr[2 * qq], pr[2 * qq + 1], 0x5410);
                sh.wx.sm[2 * npl + 1][rowl * 4 + qq] = __byte_perm(pr[2 * qq], pr[2 * qq + 1], 0x7632);
            }
        }
        __syncthreads();

        __half* Bg = g_Bh + ((size_t)e * NUM_N + (size_t)nb * 128) * NUM_K + (size_t)kb * 128;
#pragma unroll
        for (int i = 0; i < 8; i++) {
            int item = t + i * THREADS;
            int n  = item >> 4;
            int q4 = item & 15;
            uint4 v = make_uint4(sh.wx.sm[n][q4 * 4], sh.wx.sm[n][q4 * 4 + 1],
                                 sh.wx.sm[n][q4 * 4 + 2], sh.wx.sm[n][q4 * 4 + 3]);
            *reinterpret_cast<uint4*>(Bg + (size_t)n * NUM_K + q4 * 8) = v;
        }
    } else {
        // ---- aprep ----
        const int apb = j - q - 1;
        size_t i = (size_t)apb * THREADS + t;
        const float4* s4 = reinterpret_cast<const float4*>(state);
        float4 a = s4[i * 2], bb = s4[i * 2 + 1];
        __half2 h0 = __floats2half2_rn(a.x, a.y),  h1 = __floats2half2_rn(a.z, a.w);
        __half2 h2 = __floats2half2_rn(bb.x, bb.y), h3 = __floats2half2_rn(bb.z, bb.w);
        uint4 o;
        o.x = *reinterpret_cast<unsigned*>(&h0);
        o.y = *reinterpret_cast<unsigned*>(&h1);
        o.z = *reinterpret_cast<unsigned*>(&h2);
        o.w = *reinterpret_cast<unsigned*>(&h3);
        reinterpret_cast<uint4*>(g_Ah)[i] = o;
    }
}

// ---------------- asm helpers ----------------
__device__ __forceinline__ void cpa16(void* dst, const void* src) {
    unsigned d = (unsigned)__cvta_generic_to_shared(dst);
    asm volatile("cp.async.cg.shared.global [%0], [%1], 16;" :: "r"(d), "l"(src));
}
__device__ __forceinline__ void cp_commit() { asm volatile("cp.async.commit_group;"); }
template <int N>
__device__ __forceinline__ void cp_wait() { asm volatile("cp.async.wait_group %0;" :: "n"(N)); }

__device__ __forceinline__ void ldsm4(unsigned& r0, unsigned& r1, unsigned& r2, unsigned& r3,
                                      unsigned addr) {
    asm volatile("ldmatrix.sync.aligned.m8n8.x4.shared.b16 {%0,%1,%2,%3}, [%4];"
                 : "=r"(r0), "=r"(r1), "=r"(r2), "=r"(r3) : "r"(addr));
}

#define MMA_F16(d, a, b)                                                        \
    asm volatile(                                                               \
        "mma.sync.aligned.m16n8k16.row.col.f32.f16.f16.f32 "                    \
        "{%0,%1,%2,%3}, {%4,%5,%6,%7}, {%8,%9}, {%0,%1,%2,%3};"                 \
        : "+f"(d[0]), "+f"(d[1]), "+f"(d[2]), "+f"(d[3])                        \
        : "r"(a[0]), "r"(a[1]), "r"(a[2]), "r"(a[3]), "r"(b[0]), "r"(b[1]))

// ---------------- persistent grouped GEMM: BM=64, BK=32, 6-stage ring, 2 CTAs/SM -------------
__global__ __launch_bounds__(THREADS, 2)
void k_gemm(float* __restrict__ out) {
    extern __shared__ __align__(16) unsigned dsm[];
    unsigned* As = dsm;                                   // [STAGES][BM][ROWSTRIDE]
    unsigned* Bs = dsm + STAGES * A_STAGE_UINTS;          // [STAGES][BN][ROWSTRIDE]
    int*      toks = (int*)(dsm + STAGES * (A_STAGE_UINTS + B_STAGE_UINTS));

    const int tid  = threadIdx.x;
    const int wid  = tid >> 5;
    const int lane = tid & 31;
    const int wm   = (wid >> 2) * 32;    // 2x4 warp grid, 32x32 warp tiles
    const int wn   = (wid & 3) * 32;
    const int g8   = lane >> 2;          // 0..7
    const int tig  = lane & 3;           // 0..3

    // load mapping: A = 64 rows x 4 chunks (1/thread); B = 128 rows x 4 chunks (2/thread)
    const int ar = tid >> 2, ac = tid & 3;
    const int br = tid >> 1, bc2 = (tid & 1) * 2;

    // per-lane ldmatrix base addresses (stage 0), bytes
    const unsigned abase = (unsigned)__cvta_generic_to_shared(As);
    const unsigned bbase = (unsigned)__cvta_generic_to_shared(Bs);
    const int mtx = lane >> 3;           // 0..3
    const int lr  = lane & 7;
    unsigned aaddr[2];
#pragma unroll
    for (int mi = 0; mi < 2; mi++)
        aaddr[mi] = abase + (((wm + mi * 16 + (mtx & 1) * 8 + lr) * ROWSTRIDE
                              + (mtx >> 1) * 4) << 2);
    unsigned baddr[2];
#pragma unroll
    for (int nip = 0; nip < 2; nip++)
        baddr[nip] = bbase + (((wn + nip * 16 + (mtx >> 1) * 8 + lr) * ROWSTRIDE
                               + (mtx & 1) * 4) << 2);

    const int ntiles = g_nrow * (NUM_N / BN);

    for (int tl = blockIdx.x; tl < ntiles; tl += GEMM_GRID) {
        const int rt    = tl >> 4;               // row-tile (n varies fastest: A-slab L2 reuse)
        const int nbase = (tl & 15) * BN;
        const int ete   = g_rowte[rt];
        const int e     = ete >> 16;
        const int mbase = (ete & 0xFFFF) * BM;
        const int cnt   = g_counts[e];
        const int off   = g_offsets[e];

        __syncthreads();   // previous tile fully consumed (toks + smem ring reuse safe)
        if (tid < BM) {
            int gm = mbase + tid;
            toks[tid] = (gm < cnt) ? g_sorted[off + gm] : g_sorted[off];
        }
        __syncthreads();

        const __half* Bg   = g_Bh + ((size_t)e * NUM_N + nbase) * NUM_K;
        const __half* arow = g_Ah + (size_t)toks[ar] * NUM_K;
        const __half* brow = Bg + (size_t)br * NUM_K;

        auto load_stage = [&](int s, int k0) {
            cpa16(As + s * A_STAGE_UINTS + ar * ROWSTRIDE + ac * 4, arow + k0 + ac * 8);
            unsigned* b = Bs + s * B_STAGE_UINTS + br * ROWSTRIDE;
            cpa16(b + bc2 * 4,       brow + k0 + bc2 * 8);
            cpa16(b + (bc2 + 1) * 4, brow + k0 + (bc2 + 1) * 8);
        };

        float acc[2][4][4];
#pragma unroll
        for (int mi = 0; mi < 2; mi++)
#pragma unroll
            for (int ni = 0; ni < 4; ni++)
#pragma unroll
                for (int q = 0; q < 4; q++) acc[mi][ni][q] = 0.0f;

        // prologue: stages 0..4
#pragma unroll
        for (int s = 0; s < STAGES - 1; s++) { load_stage(s, s * BK); cp_commit(); }

        int s = 0;
        for (int kt = 0; kt < KITERS; kt++) {
            cp_wait<STAGES - 2>();       // stage kt resident
            __syncthreads();             // visible; oldest reusable slot free
            if (kt + STAGES - 1 < KITERS) load_stage((kt + STAGES - 1) % STAGES,
                                                     (kt + STAGES - 1) * BK);
            cp_commit();                 // uniform group counting (empty ok)

            const unsigned aoff = (unsigned)(s * A_STAGE_UINTS * 4);
            const unsigned boff = (unsigned)(s * B_STAGE_UINTS * 4);
#pragma unroll
            for (int ks = 0; ks < 2; ks++) {          // two k16 steps
                const unsigned kb = ks * 32;
                unsigned af[2][4], bf[4][2];
#pragma unroll
                for (int mi = 0; mi < 2; mi++)
                    ldsm4(af[mi][0], af[mi][1], af[mi][2], af[mi][3], aaddr[mi] + aoff + kb);
#pragma unroll
                for (int nip = 0; nip < 2; nip++)
                    ldsm4(bf[2 * nip][0], bf[2 * nip][1], bf[2 * nip + 1][0], bf[2 * nip + 1][1],
                          baddr[nip] + boff + kb);
#pragma unroll
                for (int mi = 0; mi < 2; mi++)
#pragma unroll
                    for (int ni = 0; ni < 4; ni++)
                        MMA_F16(acc[mi][ni], af[mi], bf[ni]);
            }
            if (++s == STAGES) s = 0;
        }

        // epilogue: scatter rows to out[token][n]
#pragma unroll
        for (int mi = 0; mi < 2; mi++) {
            int rl0 = wm + mi * 16 + g8;
            int rl1 = rl0 + 8;
            bool v0 = (mbase + rl0) < cnt;
            bool v1 = (mbase + rl1) < cnt;
            int tok0 = toks[rl0];
            int tok1 = toks[rl1];
#pragma unroll
            for (int ni = 0; ni < 4; ni++) {
                int c = nbase + wn + ni * 8 + tig * 2;
                if (v0) *reinterpret_cast<float2*>(&out[(size_t)tok0 * NUM_N + c]) =
                    make_float2(acc[mi][ni][0], acc[mi][ni][1]);
                if (v1) *reinterpret_cast<float2*>(&out[(size_t)tok1 * NUM_N + c]) =
                    make_float2(acc[mi][ni][2], acc[mi][ni][3]);
            }
        }
    }
}

// ---------------- launch ----------------
extern "C" void kernel_launch(void* const* d_in, const int* in_sizes, int n_in,
                              void* d_out, int out_size) {
    const float* state      = (const float*)d_in[0];
    const int*   wpacked    = (const int*)  d_in[1];
    const float* wscale     = (const float*)d_in[2];
    const int*   zp         = (const int*)  d_in[3];
    const int*   g_idx      = (const int*)  d_in[4];
    const int*   expert_ids = (const int*)  d_in[5];
    float*       out        = (float*)d_out;

    cudaFuncSetAttribute(k_gemm, cudaFuncAttributeMaxDynamicSharedMemorySize, GEMM_SMEM);

    k_prep<<<PREP_BLOCKS, THREADS>>>(state, wpacked, wscale, zp, g_idx, expert_ids);
    k_gemm<<<GEMM_GRID, THREADS, GEMM_SMEM>>>(out);
}

// round 14
// speedup vs baseline: 1.2553x; 1.2420x over previous
#include <cuda_runtime.h>
#include <cuda_fp16.h>
#include <cstdint>

#define NUM_E 8
#define NUM_T 8192
#define NUM_K 2048
#define NUM_N 2048
#define NUM_G 16

constexpr int BM = 128;
constexpr int BN = 128;
constexpr int BK = 32;       // k per main-loop iter
constexpr int BKP = BK / 2;  // k-pair uints per row = 16
constexpr int PAD = 4;       // uint row stride 20 -> conflict-free ldmatrix
constexpr int ROWSTRIDE = BKP + PAD;             // 20 uints
constexpr int STAGE_UINTS = BM * ROWSTRIDE;      // 2560 uints = 10240 B
constexpr int STAGES = 5;                        // prefetch distance 4
constexpr int THREADS = 256;
constexpr int KITERS = NUM_K / BK;               // 64
constexpr int GEMM_SMEM = (2 * STAGES * STAGE_UINTS) * 4 + BM * 4;  // 102912 B

constexpr int WX_BLOCKS = 2048;
constexpr int AP_BLOCKS = (NUM_T * NUM_K / 8) / 256;   // 8192
constexpr int PREP_BLOCKS = 1 + WX_BLOCKS + AP_BLOCKS; // 10241

// ---------------- static device scratch (no allocations allowed) ----------------
__device__ int    g_counts[NUM_E];
__device__ int    g_offsets[NUM_E];
__device__ int    g_sorted[NUM_T];
__device__ __half g_Ah[(size_t)NUM_T * NUM_K];          // state fp16, 32 MB
__device__ __half g_Bh[(size_t)NUM_E * NUM_N * NUM_K];  // dequant W [e][n][k], 64 MB

// ---------------- fused prep: route (1 block) + wexpand (2048) + aprep (8192) ----------------
__global__ __launch_bounds__(THREADS)
void k_prep(const float* __restrict__ state,
            const int*   __restrict__ wp,
            const float* __restrict__ ws,
            const int*   __restrict__ zp,
            const int*   __restrict__ gidx,
            const int*   __restrict__ expert_ids)
{
    __shared__ union {
        struct { int cnt[NUM_E]; int cur[NUM_E]; } route;
        struct {
            uint2    zs[NUM_G][64];
            int      gsh[128];
            unsigned sm[128][65];
        } wx;
    } sh;

    const int b = blockIdx.x;
    const int t = threadIdx.x;

    if (b == 0) {
        // ---- routing ----
        if (t < NUM_E) sh.route.cnt[t] = 0;
        __syncthreads();
        for (int i = t; i < NUM_T; i += THREADS) atomicAdd(&sh.route.cnt[expert_ids[i]], 1);
        __syncthreads();
        if (t == 0) {
            int acc = 0;
            for (int e = 0; e < NUM_E; e++) {
                g_counts[e] = sh.route.cnt[e]; g_offsets[e] = acc; sh.route.cur[e] = acc;
                acc += sh.route.cnt[e];
            }
        }
        __syncthreads();
        for (int i = t; i < NUM_T; i += THREADS) {
            int p = atomicAdd(&sh.route.cur[expert_ids[i]], 1);
            g_sorted[p] = i;
        }
        return;
    }

    const int j = b - 1;
    const int q = j / 5, rm = j % 5;     // interleave: 1 wexpand per 4 aprep

    if (rm == 0) {
        // ---- wexpand block q = ((e*16 + nb)*16 + kb) ----
        const int kb = q & 15;
        const int nb = (q >> 4) & 15;
        const int e  = q >> 8;

        for (int i = t; i < NUM_G * 64; i += THREADS) {
            int g = i >> 6, np = i & 63;
            const size_t base = (size_t)(e * NUM_G + g) * NUM_N + nb * 128 + 2 * np;
            unsigned z2 = (0x6400u | (unsigned)zp[base]) | ((0x6400u | (unsigned)zp[base + 1]) << 16);
            __half2 s2h = __floats2half2_rn(ws[base], ws[base + 1]);
            uint2 v; v.x = z2; v.y = *reinterpret_cast<unsigned*>(&s2h);
            sh.wx.zs[g][np] = v;
        }
        if (t < 128) sh.wx.gsh[t] = gidx[kb * 128 + t];
        __syncthreads();

        const int npl = t & 63;
        const int rq  = t >> 6;
        const int npg = nb * 64 + npl;
        const uint2* wp2 = reinterpret_cast<const uint2*>(wp + (size_t)e * (NUM_K / 8) * NUM_N);

#pragma unroll
        for (int p = 0; p < 4; p++) {
            const int rowl = rq * 4 + p;
            const int rowg = kb * 16 + rowl;
            uint2 w = wp2[(size_t)rowg * (NUM_N / 2) + npg];
            unsigned pr[8];
#pragma unroll
            for (int jj = 0; jj < 8; jj++) {
                uint2 zsv = sh.wx.zs[sh.wx.gsh[rowl * 8 + jj]][npl];
                unsigned x0 = w.x >> (4 * jj), x1 = w.y >> (4 * jj);
                unsigned h2 = ((x0 & 15u) | 0x6400u) | (((x1 & 15u) | 0x6400u) << 16);
                __half2 v = __hsub2(*reinterpret_cast<__half2*>(&h2),
                                    *reinterpret_cast<__half2*>(&zsv.x));   // exact q - zp
                v = __hmul2(v, *reinterpret_cast<__half2*>(&zsv.y));
                pr[jj] = *reinterpret_cast<unsigned*>(&v);
            }
#pragma unroll
            for (int qq = 0; qq < 4; qq++) {
                sh.wx.sm[2 * npl    ][rowl * 4 + qq] = __byte_perm(pr[2 * qq], pr[2 * qq + 1], 0x5410);
                sh.wx.sm[2 * npl + 1][rowl * 4 + qq] = __byte_perm(pr[2 * qq], pr[2 * qq + 1], 0x7632);
            }
        }
        __syncthreads();

        __half* Bg = g_Bh + ((size_t)e * NUM_N + (size_t)nb * 128) * NUM_K + (size_t)kb * 128;
#pragma unroll
        for (int i = 0; i < 8; i++) {
            int item = t + i * THREADS;
            int n  = item >> 4;
            int q4 = item & 15;
            uint4 v = make_uint4(sh.wx.sm[n][q4 * 4], sh.wx.sm[n][q4 * 4 + 1],
                                 sh.wx.sm[n][q4 * 4 + 2], sh.wx.sm[n][q4 * 4 + 3]);
            *reinterpret_cast<uint4*>(Bg + (size_t)n * NUM_K + q4 * 8) = v;
        }
    } else {
        // ---- aprep ----
        const int apb = j - q - 1;
        size_t i = (size_t)apb * THREADS + t;        // over T*K/8
        const float4* s4 = reinterpret_cast<const float4*>(state);
        float4 a = s4[i * 2], bb = s4[i * 2 + 1];
        __half2 h0 = __floats2half2_rn(a.x, a.y),  h1 = __floats2half2_rn(a.z, a.w);
        __half2 h2 = __floats2half2_rn(bb.x, bb.y), h3 = __floats2half2_rn(bb.z, bb.w);
        uint4 o;
        o.x = *reinterpret_cast<unsigned*>(&h0);
        o.y = *reinterpret_cast<unsigned*>(&h1);
        o.z = *reinterpret_cast<unsigned*>(&h2);
        o.w = *reinterpret_cast<unsigned*>(&h3);
        reinterpret_cast<uint4*>(g_Ah)[i] = o;
    }
}

// ---------------- asm helpers ----------------
__device__ __forceinline__ void cpa16(void* dst, const void* src) {
    unsigned d = (unsigned)__cvta_generic_to_shared(dst);
    asm volatile("cp.async.cg.shared.global [%0], [%1], 16;" :: "r"(d), "l"(src));
}
__device__ __forceinline__ void cp_commit() { asm volatile("cp.async.commit_group;"); }
template <int N>
__device__ __forceinline__ void cp_wait() { asm volatile("cp.async.wait_group %0;" :: "n"(N)); }

__device__ __forceinline__ void ldsm4(unsigned& r0, unsigned& r1, unsigned& r2, unsigned& r3,
                                      unsigned addr) {
    asm volatile("ldmatrix.sync.aligned.m8n8.x4.shared.b16 {%0,%1,%2,%3}, [%4];"
                 : "=r"(r0), "=r"(r1), "=r"(r2), "=r"(r3) : "r"(addr));
}

#define MMA_F16(d, a, b)                                                        \
    asm volatile(                                                               \
        "mma.sync.aligned.m16n8k16.row.col.f32.f16.f16.f32 "                    \
        "{%0,%1,%2,%3}, {%4,%5,%6,%7}, {%8,%9}, {%0,%1,%2,%3};"                 \
        : "+f"(d[0]), "+f"(d[1]), "+f"(d[2]), "+f"(d[3])                        \
        : "r"(a[0]), "r"(a[1]), "r"(a[2]), "r"(a[3]), "r"(b[0]), "r"(b[1]))

// ---------------- grouped GEMM: R10 engine, 5-stage cp.async ring ----------------
__global__ __launch_bounds__(THREADS, 2)
void k_gemm(float* __restrict__ out) {
    const int e     = blockIdx.z;
    const int cnt   = g_counts[e];
    const int mbase = blockIdx.y * BM;
    if (mbase >= cnt) return;
    const int off   = g_offsets[e];
    const int nbase = blockIdx.x * BN;

    extern __shared__ __align__(16) unsigned dsm[];
    unsigned* As = dsm;                              // [STAGES][BM][ROWSTRIDE]
    unsigned* Bs = dsm + STAGES * STAGE_UINTS;       // [STAGES][BN][ROWSTRIDE]
    int*      toks = (int*)(dsm + 2 * STAGES * STAGE_UINTS);

    const int tid  = threadIdx.x;
    const int wid  = tid >> 5;
    const int lane = tid & 31;
    const int wm   = (wid >> 2) * 64;
    const int wn   = (wid & 3) * 32;
    const int g8   = lane >> 2;          // 0..7
    const int tig  = lane & 3;           // 0..3

    if (tid < BM) {
        int gm = mbase + tid;
        toks[tid] = (gm < cnt) ? g_sorted[off + gm] : g_sorted[off];
    }
    __syncthreads();

    const int r  = tid >> 1;                       // 0..127 (row for loads)
    const int kc = (tid & 1) * 2;                  // 16B chunk base

    const __half* Bg   = g_Bh + ((size_t)e * NUM_N + nbase) * NUM_K;
    const __half* arow = g_Ah + (size_t)toks[r] * NUM_K;
    const __half* brow = Bg + (size_t)r * NUM_K;

    auto load_stage = [&](int s, int k0) {
        unsigned* a = As + s * STAGE_UINTS + r * ROWSTRIDE;
        cpa16(a + kc * 4,       arow + k0 + kc * 8);
        cpa16(a + (kc + 1) * 4, arow + k0 + (kc + 1) * 8);
        unsigned* b = Bs + s * STAGE_UINTS + r * ROWSTRIDE;
        cpa16(b + kc * 4,       brow + k0 + kc * 8);
        cpa16(b + (kc + 1) * 4, brow + k0 + (kc + 1) * 8);
    };

    // per-lane ldmatrix base addresses (stage 0, ks 0), bytes
    const unsigned abase = (unsigned)__cvta_generic_to_shared(As);
    const unsigned bbase = (unsigned)__cvta_generic_to_shared(Bs);
    const int mtx = lane >> 3;           // 0..3
    const int lr  = lane & 7;
    unsigned aaddr[4];
#pragma unroll
    for (int mi = 0; mi < 4; mi++)
        aaddr[mi] = abase + (((wm + mi * 16 + (mtx & 1) * 8 + lr) * ROWSTRIDE
                              + (mtx >> 1) * 4) << 2);
    unsigned baddr[2];
#pragma unroll
    for (int nip = 0; nip < 2; nip++)
        baddr[nip] = bbase + (((wn + nip * 16 + (mtx >> 1) * 8 + lr) * ROWSTRIDE
                               + (mtx & 1) * 4) << 2);

    float acc[4][4][4];
#pragma unroll
    for (int mi = 0; mi < 4; mi++)
#pragma unroll
        for (int ni = 0; ni < 4; ni++)
#pragma unroll
            for (int q = 0; q < 4; q++) acc[mi][ni][q] = 0.0f;

    // prologue: stages 0..3
#pragma unroll
    for (int s = 0; s < STAGES - 1; s++) { load_stage(s, s * BK); cp_commit(); }

    int s = 0;
    for (int kt = 0; kt < KITERS; kt++) {
        cp_wait<STAGES - 2>();           // stage kt complete
        __syncthreads();                 // oldest reusable slot free; stage kt data visible
        if (kt + STAGES - 1 < KITERS) load_stage((kt + STAGES - 1) % STAGES,
                                                 (kt + STAGES - 1) * BK);
        cp_commit();                     // uniform group counting (empty group ok)

        const unsigned soff = (unsigned)(s * STAGE_UINTS * 4);
#pragma unroll
        for (int ks = 0; ks < 2; ks++) {            // two k16 steps
            const unsigned koff = soff + ks * 32;   // 8 uints = 32 B
            unsigned af[4][4], bf[4][2];
#pragma unroll
            for (int mi = 0; mi < 4; mi++)
                ldsm4(af[mi][0], af[mi][1], af[mi][2], af[mi][3], aaddr[mi] + koff);
#pragma unroll
            for (int nip = 0; nip < 2; nip++)
                ldsm4(bf[2 * nip][0], bf[2 * nip][1], bf[2 * nip + 1][0], bf[2 * nip + 1][1],
                      baddr[nip] + koff);
#pragma unroll
            for (int mi = 0; mi < 4; mi++)
#pragma unroll
                for (int ni = 0; ni < 4; ni++)
                    MMA_F16(acc[mi][ni], af[mi], bf[ni]);
        }
        if (++s == STAGES) s = 0;
    }

    // epilogue: scatter rows to out[token][n]
#pragma unroll
    for (int mi = 0; mi < 4; mi++) {
        int rl0 = wm + mi * 16 + g8;
        int rl1 = rl0 + 8;
        bool v0 = (mbase + rl0) < cnt;
        bool v1 = (mbase + rl1) < cnt;
        int tok0 = toks[rl0];
        int tok1 = toks[rl1];
#pragma unroll
        for (int ni = 0; ni < 4; ni++) {
            int c = nbase + wn + ni * 8 + tig * 2;
            if (v0) *reinterpret_cast<float2*>(&out[(size_t)tok0 * NUM_N + c]) =
                make_float2(acc[mi][ni][0], acc[mi][ni][1]);
            if (v1) *reinterpret_cast<float2*>(&out[(size_t)tok1 * NUM_N + c]) =
                make_float2(acc[mi][ni][2], acc[mi][ni][3]);
        }
    }
}

// ---------------- launch ----------------
extern "C" void kernel_launch(void* const* d_in, const int* in_sizes, int n_in,
                              void* d_out, int out_size) {
    const float* state      = (const float*)d_in[0];
    const int*   wpacked    = (const int*)  d_in[1];
    const float* wscale     = (const float*)d_in[2];
    const int*   zp         = (const int*)  d_in[3];
    const int*   g_idx      = (const int*)  d_in[4];
    const int*   expert_ids = (const int*)  d_in[5];
    float*       out        = (float*)d_out;

    cudaFuncSetAttribute(k_gemm, cudaFuncAttributeMaxDynamicSharedMemorySize, GEMM_SMEM);

    k_prep<<<PREP_BLOCKS, THREADS>>>(state, wpacked, wscale, zp, g_idx, expert_ids);

    dim3 grid(NUM_N / BN, NUM_T / BM, NUM_E);
    k_gemm<<<grid, THREADS, GEMM_SMEM>>>(out);
}